// round 3
// baseline (speedup 1.0000x reference)
#include <cuda_runtime.h>
#include <cuda_bf16.h>

// ---------------- problem constants ----------------
#define BB      4
#define TT      128
#define THIST   120
#define NSTEPS  8
#define DM      512
#define NH      8
#define DH      64
#define DFF     2048
#define DIN     32
#define NL      4
#define NSUB    5

#define SCALE_EMB 22.627416997969522f   // sqrt(512)
#define NEG_INF  (-3.402823466e38f)
#define LN10000  9.210340371976184f

// ---------------- device scratch (static, no allocation) ----------------
__device__ float g_buf [BB*TT*DIN];     // token buffer
__device__ float g_h   [BB*TT*DM];      // hidden states
__device__ float g_q   [BB*TT*DM];
__device__ float g_k   [BB*TT*DM];
__device__ float g_v   [BB*TT*DM];
__device__ float g_attn[BB*TT*DM];
__device__ float g_tmp [BB*TT*DM];
__device__ float g_ff  [BB*TT*DFF];
__device__ float g_part[4*BB*TT*DM];    // split-K partials for W2 (4 MB)
__device__ float g_wfused [DFF*DIN];    // scale * Wr1[:, :512] @ W_emb
__device__ float g_ctxterm[BB*DFF];     // Wr1[:,512:]@ctx + scale*Wr1[:,:512]@b_emb + br1

// ---------------- helpers ----------------
__device__ __forceinline__ float gelu_tanh(float x) {
    float x3 = x * x * x;
    float t  = tanhf(0.7978845608028654f * (x + 0.044715f * x3));
    return 0.5f * x * (1.0f + t);
}

// ---------------- init: buf = [history ; zeros] ----------------
__global__ void init_kernel(const float* __restrict__ hist) {
    int idx = blockIdx.x * 256 + threadIdx.x;           // 16384 total
    if (idx >= BB*TT*DIN) return;
    int b = idx >> 12;            // / (128*32)
    int t = (idx >> 5) & 127;
    int k = idx & 31;
    g_buf[idx] = (t < THIST) ? hist[(b*THIST + t)*DIN + k] : 0.0f;
}

// ---------------- precompute Wfused = scale * Wr1[:, :512] @ W_emb ----------------
__global__ void wfused_kernel(const float* __restrict__ Wr1, const float* __restrict__ Wemb) {
    int idx = blockIdx.x * 256 + threadIdx.x;           // 65536 total
    int i = idx >> 5;       // 0..2047
    int m = idx & 31;       // 0..31
    const float* w = Wr1 + (size_t)i * (2*DM);
    float s = 0.0f;
    #pragma unroll 8
    for (int j = 0; j < DM; j++) s += w[j] * Wemb[j*DIN + m];
    g_wfused[i*DIN + m] = s * SCALE_EMB;
}

// ---------------- embedding + positional encoding ----------------
// h[b,t,d] = (buf[b,t,:] . W_emb[d,:] + b_emb[d]) * scale + pe[t,d]
__global__ void embed_kernel(const float* __restrict__ Wemb, const float* __restrict__ bemb) {
    int bt = blockIdx.x;                 // 0..511
    int t  = bt & 127;
    __shared__ float row[DIN];
    if (threadIdx.x < DIN) row[threadIdx.x] = g_buf[bt*DIN + threadIdx.x];
    __syncthreads();
    for (int d = threadIdx.x; d < DM; d += blockDim.x) {
        float s = bemb[d];
        const float* w = Wemb + d*DIN;
        #pragma unroll
        for (int k = 0; k < DIN; k++) s += row[k] * w[k];
        int i = d >> 1;
        float div = expf((float)(2*i) * (-LN10000 / (float)DM));
        float ang = (float)t * div;
        float pe  = (d & 1) ? cosf(ang) : sinf(ang);
        g_h[bt*DM + d] = s * SCALE_EMB + pe;
    }
}

// ---------------- shared tile body for 64x64 NT SGEMM over a K chunk ----------------
// Computes acc[4][4] for C tile (m0,n0) from A[*, kbeg:kbeg+klen] (row stride lda)
// and W[*, kbeg:kbeg+klen] (row stride ldw). 256 threads.
__device__ __forceinline__ void gemm_tile_body(
    const float* __restrict__ A, const float* __restrict__ W,
    int lda, int ldw, int kbeg, int klen,
    int m0, int n0, float acc[4][4],
    float (*As)[64], float (*Bs)[64])
{
    int tid = threadIdx.x;
    int lm = tid >> 2;          // 0..63
    int lk = (tid & 3) * 4;     // 0,4,8,12
    const float* Aptr = A + (size_t)(m0 + lm) * lda + kbeg + lk;
    const float* Wptr = W + (size_t)(n0 + lm) * ldw + kbeg + lk;
    int tx = tid & 15, ty = tid >> 4;

    for (int k0 = 0; k0 < klen; k0 += 16) {
        float4 a4 = *(const float4*)(Aptr + k0);
        float4 b4 = *(const float4*)(Wptr + k0);
        As[lk+0][lm] = a4.x; As[lk+1][lm] = a4.y; As[lk+2][lm] = a4.z; As[lk+3][lm] = a4.w;
        Bs[lk+0][lm] = b4.x; Bs[lk+1][lm] = b4.y; Bs[lk+2][lm] = b4.z; Bs[lk+3][lm] = b4.w;
        __syncthreads();
        #pragma unroll
        for (int kk = 0; kk < 16; kk++) {
            float4 av = *(const float4*)&As[kk][ty*4];
            float4 bv = *(const float4*)&Bs[kk][tx*4];
            float a[4] = {av.x, av.y, av.z, av.w};
            float b[4] = {bv.x, bv.y, bv.z, bv.w};
            #pragma unroll
            for (int i = 0; i < 4; i++)
                #pragma unroll
                for (int j = 0; j < 4; j++)
                    acc[i][j] = fmaf(a[i], b[j], acc[i][j]);
        }
        __syncthreads();
    }
}

// ---------------- general NT SGEMM:  C[M,N] = A[M,K] @ W[N,K]^T  (+ epilogue) ----------------
// MODE 0: C = AB + bias        MODE 1: C = gelu(AB + bias)       MODE 2: C = AB + bias + R
template <int MODE>
__global__ __launch_bounds__(256)
void gemm_nt(const float* __restrict__ A, const float* __restrict__ W,
             const float* __restrict__ bias, const float* __restrict__ R,
             float* __restrict__ C, int M, int N, int K)
{
    __shared__ float As[16][64];
    __shared__ float Bs[16][64];
    int m0 = blockIdx.y * 64, n0 = blockIdx.x * 64;
    float acc[4][4] = {};
    gemm_tile_body(A, W, K, K, 0, K, m0, n0, acc, As, Bs);

    int tid = threadIdx.x;
    int tx = tid & 15, ty = tid >> 4;
    #pragma unroll
    for (int i = 0; i < 4; i++) {
        int m = m0 + ty*4 + i;
        #pragma unroll
        for (int j = 0; j < 4; j++) {
            int n = n0 + tx*4 + j;
            float v = acc[i][j];
            if (bias) v += bias[n];
            if (MODE == 1) v = gelu_tanh(v);
            if (MODE == 2) v += R[(size_t)m * N + n];
            C[(size_t)m * N + n] = v;
        }
    }
}

// ---------------- fused Q/K/V projection: blockIdx.z selects which ----------------
// M=N=K=512; no bias. 192 CTAs in one launch.
__global__ __launch_bounds__(256)
void gemm_qkv(const float* __restrict__ A,
              const float* __restrict__ Wq, const float* __restrict__ Wk,
              const float* __restrict__ Wv)
{
    __shared__ float As[16][64];
    __shared__ float Bs[16][64];
    int z = blockIdx.z;
    const float* W = (z == 0) ? Wq : (z == 1) ? Wk : Wv;
    float* C = (z == 0) ? g_q : (z == 1) ? g_k : g_v;

    int m0 = blockIdx.y * 64, n0 = blockIdx.x * 64;
    float acc[4][4] = {};
    gemm_tile_body(A, W, DM, DM, 0, DM, m0, n0, acc, As, Bs);

    int tid = threadIdx.x;
    int tx = tid & 15, ty = tid >> 4;
    #pragma unroll
    for (int i = 0; i < 4; i++) {
        int m = m0 + ty*4 + i;
        #pragma unroll
        for (int j = 0; j < 4; j++)
            C[(size_t)m * DM + n0 + tx*4 + j] = acc[i][j];
    }
}

// ---------------- split-K GEMM for W2: K=2048 split into 4 slices of 512 ----------------
// part[z][m][n] = A[m, z*512:(z+1)*512] @ W[n, z*512:(z+1)*512]^T. 256 CTAs.
__global__ __launch_bounds__(256)
void gemm_w2_splitk(const float* __restrict__ A, const float* __restrict__ W)
{
    __shared__ float As[16][64];
    __shared__ float Bs[16][64];
    int z = blockIdx.z;
    int m0 = blockIdx.y * 64, n0 = blockIdx.x * 64;
    float acc[4][4] = {};
    gemm_tile_body(A, W, DFF, DFF, z*512, 512, m0, n0, acc, As, Bs);

    float* part = g_part + (size_t)z * (BB*TT*DM);
    int tid = threadIdx.x;
    int tx = tid & 15, ty = tid >> 4;
    #pragma unroll
    for (int i = 0; i < 4; i++) {
        int m = m0 + ty*4 + i;
        #pragma unroll
        for (int j = 0; j < 4; j++)
            part[(size_t)m * DM + n0 + tx*4 + j] = acc[i][j];
    }
}

// ---------------- attention: one block per (q, head, batch) ----------------
// mask keeps keys with k > q (anti-causal, faithful to reference). q=T-1 -> uniform.
__global__ __launch_bounds__(128)
void attn_kernel() {
    int qi = blockIdx.x;     // 0..127
    int hh = blockIdx.y;     // 0..7
    int b  = blockIdx.z;     // 0..3
    int tid = threadIdx.x;   // 128

    __shared__ float qs[DH];
    __shared__ float w[TT];
    __shared__ float r[TT];

    const float* qrow = g_q + (size_t)(b*TT + qi)*DM + hh*DH;
    if (tid < DH) qs[tid] = qrow[tid];
    __syncthreads();

    const float* krow = g_k + (size_t)(b*TT + tid)*DM + hh*DH;
    float s = 0.0f;
    #pragma unroll 16
    for (int d = 0; d < DH; d++) s += qs[d] * krow[d];
    float lg = (tid > qi) ? s * 0.125f : NEG_INF;   // finite min, like jnp.finfo.min

    r[tid] = lg; __syncthreads();
    for (int off = 64; off > 0; off >>= 1) {
        if (tid < off) r[tid] = fmaxf(r[tid], r[tid+off]);
        __syncthreads();
    }
    float m = r[0]; __syncthreads();

    float e = expf(lg - m);                          // finite-min => exp(0)=1 row at q=T-1
    w[tid] = e; r[tid] = e; __syncthreads();
    for (int off = 64; off > 0; off >>= 1) {
        if (tid < off) r[tid] += r[tid+off];
        __syncthreads();
    }
    float inv = 1.0f / r[0];
    __syncthreads();

    if (tid < DH) {
        const float* vcol = g_v + (size_t)b*TT*DM + hh*DH + tid;
        float acc = 0.0f;
        #pragma unroll 8
        for (int j = 0; j < TT; j++) acc += w[j] * vcol[(size_t)j*DM];
        g_attn[(size_t)(b*TT + qi)*DM + hh*DH + tid] = acc * inv;
    }
}

// ---------------- layernorm over rows of 512 ----------------
// PART==0: x = X[row]                 (X already holds residual+bias from MODE2 gemm)
// PART==1: x = X[row] + bias + sum_z g_part[z][row]   (fused split-K reduction)
template <int PART>
__global__ __launch_bounds__(256)
void ln_kernel(const float* __restrict__ X, const float* __restrict__ bias,
               const float* __restrict__ gg, const float* __restrict__ bb,
               float* __restrict__ O)
{
    int rrow = blockIdx.x, tid = threadIdx.x;
    const float* x = X + (size_t)rrow * DM;
    float x0 = x[tid], x1 = x[tid + 256];
    if (PART) {
        x0 += bias[tid];
        x1 += bias[tid + 256];
        #pragma unroll
        for (int z = 0; z < 4; z++) {
            const float* p = g_part + (size_t)z*(BB*TT*DM) + (size_t)rrow*DM;
            x0 += p[tid];
            x1 += p[tid + 256];
        }
    }

    __shared__ float red[8];
    __shared__ float stats[2];
    int lane = tid & 31, warp = tid >> 5;

    float s = x0 + x1;
    for (int off = 16; off; off >>= 1) s += __shfl_down_sync(0xffffffffu, s, off);
    if (!lane) red[warp] = s;
    __syncthreads();
    if (tid == 0) {
        float t = 0; for (int i = 0; i < 8; i++) t += red[i];
        stats[0] = t * (1.0f / DM);
    }
    __syncthreads();
    float mu = stats[0];
    float d0 = x0 - mu, d1 = x1 - mu;
    s = d0*d0 + d1*d1;
    __syncthreads();   // protect red[] reuse
    for (int off = 16; off; off >>= 1) s += __shfl_down_sync(0xffffffffu, s, off);
    if (!lane) red[warp] = s;
    __syncthreads();
    if (tid == 0) {
        float t = 0; for (int i = 0; i < 8; i++) t += red[i];
        stats[1] = rsqrtf(t * (1.0f / DM) + 1e-5f);
    }
    __syncthreads();
    float rstd = stats[1];
    O[(size_t)rrow*DM + tid]       = d0 * rstd * gg[tid]       + bb[tid];
    O[(size_t)rrow*DM + tid + 256] = d1 * rstd * gg[tid + 256] + bb[tid + 256];
}

// ---------------- ctx-term for refine: per (b, i) row ----------------
// g_ctxterm[b,i] = Wr1[i,512:1024] . h[b,ptr-1,:] + scale * Wr1[i,0:512] . b_emb + br1[i]
__global__ __launch_bounds__(256)
void ctxterm_kernel(const float* __restrict__ Wr1, const float* __restrict__ br1,
                    const float* __restrict__ bemb, int step)
{
    int ridx = blockIdx.x * 8 + (threadIdx.x >> 5);   // 0..8191
    int lane = threadIdx.x & 31;
    int b = ridx >> 11;
    int i = ridx & 2047;
    int ptr = THIST + step;
    const float* ctx = g_h + (size_t)(b*TT + ptr - 1)*DM;
    const float* w1  = Wr1 + (size_t)i * (2*DM);
    float s1 = 0.0f, s2 = 0.0f;
    for (int j = lane; j < DM; j += 32) {
        s1 += w1[j]      * bemb[j];
        s2 += w1[DM + j] * ctx[j];
    }
    for (int off = 16; off; off >>= 1) {
        s1 += __shfl_down_sync(0xffffffffu, s1, off);
        s2 += __shfl_down_sync(0xffffffffu, s2, off);
    }
    if (lane == 0) g_ctxterm[b*DFF + i] = s2 + SCALE_EMB * s1 + br1[i];
}

// ---------------- refine loop: one block per batch ----------------
__global__ __launch_bounds__(256)
void refine_kernel(const float* __restrict__ Wr2, const float* __restrict__ br2,
                   float* __restrict__ out, int step)
{
    int b = blockIdx.x;
    int tid = threadIdx.x;
    int ptr = THIST + step;

    __shared__ float cur[DIN];
    __shared__ float gact[DFF];

    if (tid < DIN) cur[tid] = g_buf[(size_t)(b*TT + ptr - 1)*DIN + tid];
    __syncthreads();

    for (int it = 0; it < NSUB; it++) {
        // t = ctxterm + Wfused @ cur ; gact = gelu(t)
        for (int i = tid; i < DFF; i += 256) {
            float s = g_ctxterm[b*DFF + i];
            const float* wf = g_wfused + i*DIN;
            #pragma unroll
            for (int m = 0; m < DIN; m++) s += wf[m] * cur[m];
            gact[i] = gelu_tanh(s);
        }
        __syncthreads();
        // delta = Wr2 @ gact + br2 ; cur += delta   (warp w -> rows 4w..4w+3)
        int warp = tid >> 5, lane = tid & 31;
        for (int m = warp*4; m < warp*4 + 4; m++) {
            float s = 0.0f;
            for (int i = lane; i < DFF; i += 32) s += Wr2[(size_t)m*DFF + i] * gact[i];
            for (int off = 16; off; off >>= 1) s += __shfl_down_sync(0xffffffffu, s, off);
            if (lane == 0) cur[m] += s + br2[m];
        }
        __syncthreads();
    }

    if (tid < DIN) {
        float v = cur[tid];
        g_buf[(size_t)(b*TT + ptr)*DIN + tid] = v;
        out[(size_t)(b*NSTEPS + step)*DIN + tid] = v;
    }
}

// ---------------- host orchestration ----------------
extern "C" void kernel_launch(void* const* d_in, const int* in_sizes, int n_in,
                              void* d_out, int out_size)
{
    const float* hist = (const float*)d_in[0];
    // d_in[1] = steps (int), fixed at 8
    const float* Wemb = (const float*)d_in[2];
    const float* bemb = (const float*)d_in[3];
    const float* Wq   = (const float*)d_in[4];
    const float* Wk   = (const float*)d_in[5];
    const float* Wv   = (const float*)d_in[6];
    const float* Wo   = (const float*)d_in[7];
    const float* ln1g = (const float*)d_in[8];
    const float* ln1b = (const float*)d_in[9];
    const float* W1   = (const float*)d_in[10];
    const float* b1   = (const float*)d_in[11];
    const float* W2   = (const float*)d_in[12];
    const float* b2   = (const float*)d_in[13];
    const float* ln2g = (const float*)d_in[14];
    const float* ln2b = (const float*)d_in[15];
    const float* Wr1  = (const float*)d_in[16];
    const float* br1  = (const float*)d_in[17];
    const float* Wr2  = (const float*)d_in[18];
    const float* br2  = (const float*)d_in[19];
    float* out = (float*)d_out;

    float *p_h, *p_attn, *p_tmp, *p_ff;
    cudaGetSymbolAddress((void**)&p_h,    g_h);
    cudaGetSymbolAddress((void**)&p_attn, g_attn);
    cudaGetSymbolAddress((void**)&p_tmp,  g_tmp);
    cudaGetSymbolAddress((void**)&p_ff,   g_ff);

    const int M = BB * TT;   // 512

    init_kernel<<<64, 256>>>(hist);
    wfused_kernel<<<256, 256>>>(Wr1, Wemb);

    for (int step = 0; step < NSTEPS; step++) {
        embed_kernel<<<M, 128>>>(Wemb, bemb);

        for (int l = 0; l < NL; l++) {
            const float* wq = Wq + (size_t)l*DM*DM;
            const float* wk = Wk + (size_t)l*DM*DM;
            const float* wv = Wv + (size_t)l*DM*DM;
            const float* wo = Wo + (size_t)l*DM*DM;
            const float* w1 = W1 + (size_t)l*DFF*DM;
            const float* w2 = W2 + (size_t)l*DM*DFF;

            dim3 gqkv(DM/64, M/64, 3);  // 192 CTAs, one launch
            dim3 g512(DM/64, M/64);     // (8, 8)
            dim3 gff(DFF/64, M/64);     // (32, 8) = 256 CTAs
            dim3 gw2(DM/64, M/64, 4);   // split-K: 256 CTAs

            gemm_qkv<<<gqkv, 256>>>(p_h, wq, wk, wv);
            attn_kernel<<<dim3(TT, NH, BB), 128>>>();

            gemm_nt<2><<<g512, 256>>>(p_attn, wo, nullptr, p_h, p_tmp, M, DM, DM);
            ln_kernel<0><<<M, 256>>>(p_tmp, nullptr, ln1g + l*DM, ln1b + l*DM, p_h);

            gemm_nt<1><<<gff, 256>>>(p_h, w1, b1 + l*DFF, nullptr, p_ff, M, DFF, DM);
            gemm_w2_splitk<<<gw2, 256>>>(p_ff, w2);
            ln_kernel<1><<<M, 256>>>(p_h, b2 + l*DM, ln2g + l*DM, ln2b + l*DM, p_h);
        }

        ctxterm_kernel<<<1024, 256>>>(Wr1, br1, bemb, step);
        refine_kernel<<<BB, 256>>>(Wr2, br2, out, step);
    }
}

// round 4
// speedup vs baseline: 1.2845x; 1.2845x over previous
#include <cuda_runtime.h>
#include <cuda_bf16.h>
#include <cstdint>

// ---------------- problem constants ----------------
#define BB      4
#define TT      128
#define THIST   120
#define NSTEPS  8
#define DM      512
#define NH      8
#define DH      64
#define DFF     2048
#define DIN     32
#define NL      4
#define NSUB    5

#define SCALE_EMB 22.627416997969522f   // sqrt(512)
#define NEG_INF  (-3.402823466e38f)
#define LN10000  9.210340371976184f

// ---------------- device scratch (static, no allocation) ----------------
__device__ float g_buf [BB*TT*DIN];     // token buffer
__device__ float g_h   [BB*TT*DM];      // hidden states
__device__ float g_q   [BB*TT*DM];
__device__ float g_k   [BB*TT*DM];
__device__ float g_v   [BB*TT*DM];
__device__ float g_attn[BB*TT*DM];
__device__ float g_tmp [BB*TT*DM];
__device__ float g_ff  [BB*TT*DFF];
__device__ float g_part[4*BB*TT*DM];    // split-K partials for W2 (4 MB)
__device__ float g_wfused [DFF*DIN];    // scale * Wr1[:, :512] @ W_emb
__device__ float g_ctxterm[BB*DFF];     // Wr1[:,512:]@ctx + scale*Wr1[:,:512]@b_emb + br1

// ---------------- helpers ----------------
__device__ __forceinline__ float gelu_tanh(float x) {
    float x3 = x * x * x;
    float t  = tanhf(0.7978845608028654f * (x + 0.044715f * x3));
    return 0.5f * x * (1.0f + t);
}

__device__ __forceinline__ uint32_t f2tf32(float x) {
    uint32_t r;
    asm("cvt.rna.tf32.f32 %0, %1;" : "=r"(r) : "f"(x));
    return r;
}

__device__ __forceinline__ void mma_tf32(float c[4],
    uint32_t a0, uint32_t a1, uint32_t a2, uint32_t a3,
    uint32_t b0, uint32_t b1)
{
    asm volatile(
        "mma.sync.aligned.m16n8k8.row.col.f32.tf32.tf32.f32 "
        "{%0,%1,%2,%3}, {%4,%5,%6,%7}, {%8,%9}, {%0,%1,%2,%3};"
        : "+f"(c[0]), "+f"(c[1]), "+f"(c[2]), "+f"(c[3])
        : "r"(a0), "r"(a1), "r"(a2), "r"(a3), "r"(b0), "r"(b1));
}

// ---------------- init: buf = [history ; zeros] ----------------
__global__ void init_kernel(const float* __restrict__ hist) {
    int idx = blockIdx.x * 256 + threadIdx.x;
    if (idx >= BB*TT*DIN) return;
    int b = idx >> 12;
    int t = (idx >> 5) & 127;
    int k = idx & 31;
    g_buf[idx] = (t < THIST) ? hist[(b*THIST + t)*DIN + k] : 0.0f;
}

// ---------------- precompute Wfused = scale * Wr1[:, :512] @ W_emb ----------------
__global__ void wfused_kernel(const float* __restrict__ Wr1, const float* __restrict__ Wemb) {
    int idx = blockIdx.x * 256 + threadIdx.x;
    int i = idx >> 5;
    int m = idx & 31;
    const float* w = Wr1 + (size_t)i * (2*DM);
    float s = 0.0f;
    #pragma unroll 8
    for (int j = 0; j < DM; j++) s += w[j] * Wemb[j*DIN + m];
    g_wfused[i*DIN + m] = s * SCALE_EMB;
}

// ---------------- embedding + positional encoding ----------------
__global__ void embed_kernel(const float* __restrict__ Wemb, const float* __restrict__ bemb) {
    int bt = blockIdx.x;                 // 0..511
    int t  = bt & 127;
    __shared__ float row[DIN];
    if (threadIdx.x < DIN) row[threadIdx.x] = g_buf[bt*DIN + threadIdx.x];
    __syncthreads();
    for (int d = threadIdx.x; d < DM; d += blockDim.x) {
        float s = bemb[d];
        const float* w = Wemb + d*DIN;
        #pragma unroll
        for (int k = 0; k < DIN; k++) s += row[k] * w[k];
        int i = d >> 1;
        float div = expf((float)(2*i) * (-LN10000 / (float)DM));
        float ang = (float)t * div;
        float pe  = (d & 1) ? cosf(ang) : sinf(ang);
        g_h[bt*DM + d] = s * SCALE_EMB + pe;
    }
}

// ================= tf32 tensor-core tile body =================
// CTA = 128 threads (4 warps, 2x2 warp grid), tile 64x64, K chunk 16.
// acc[mi][ni][4]: warp computes a 32x32 sub-tile (2 m16 blocks x 4 n8 blocks).
// A row-major [*, lda], W row-major [N, ldw] (NT gemm). Smem stride 20 floats
// (pad 4) -> bank-conflict-free for both A-frag and B-frag read patterns.
#define SM_STRIDE 20

__device__ __forceinline__ void gemm_tc_body(
    const float* __restrict__ A, const float* __restrict__ W,
    int lda, int ldw, int kbeg, int klen,
    int m0, int n0, float acc[2][4][4],
    uint32_t (*As)[SM_STRIDE], uint32_t (*Bs)[SM_STRIDE])
{
    int tid  = threadIdx.x;       // 0..127
    int lane = tid & 31;
    int wrp  = tid >> 5;
    int wm0 = (wrp >> 1) * 32;
    int wn0 = (wrp & 1) * 32;

    // loader mapping: 256 float4 per 64x16 chunk; thread handles f4-idx {tid, tid+128}
    int lrow = tid >> 2;          // 0..31 ; second element row+32
    int lkq  = (tid & 3) * 4;     // k offset of float4

    const float* Ab = A + (size_t)(m0 + lrow) * lda + kbeg + lkq;
    const float* Wb = W + (size_t)(n0 + lrow) * ldw + kbeg + lkq;
    const float* Ab2 = Ab + (size_t)32 * lda;
    const float* Wb2 = Wb + (size_t)32 * ldw;

    float4 pa0, pa1, pb0, pb1;
    // prologue: fetch chunk 0
    pa0 = *(const float4*)(Ab);  pa1 = *(const float4*)(Ab2);
    pb0 = *(const float4*)(Wb);  pb1 = *(const float4*)(Wb2);

    for (int kc = 0; kc < klen; kc += 16) {
        __syncthreads();   // smem consumed by previous iter's compute
        // store current chunk (cvt to tf32 bits)
        As[lrow   ][lkq+0] = f2tf32(pa0.x); As[lrow   ][lkq+1] = f2tf32(pa0.y);
        As[lrow   ][lkq+2] = f2tf32(pa0.z); As[lrow   ][lkq+3] = f2tf32(pa0.w);
        As[lrow+32][lkq+0] = f2tf32(pa1.x); As[lrow+32][lkq+1] = f2tf32(pa1.y);
        As[lrow+32][lkq+2] = f2tf32(pa1.z); As[lrow+32][lkq+3] = f2tf32(pa1.w);
        Bs[lrow   ][lkq+0] = f2tf32(pb0.x); Bs[lrow   ][lkq+1] = f2tf32(pb0.y);
        Bs[lrow   ][lkq+2] = f2tf32(pb0.z); Bs[lrow   ][lkq+3] = f2tf32(pb0.w);
        Bs[lrow+32][lkq+0] = f2tf32(pb1.x); Bs[lrow+32][lkq+1] = f2tf32(pb1.y);
        Bs[lrow+32][lkq+2] = f2tf32(pb1.z); Bs[lrow+32][lkq+3] = f2tf32(pb1.w);
        __syncthreads();

        // prefetch next chunk (overlaps with mma below)
        if (kc + 16 < klen) {
            pa0 = *(const float4*)(Ab  + kc + 16);
            pa1 = *(const float4*)(Ab2 + kc + 16);
            pb0 = *(const float4*)(Wb  + kc + 16);
            pb1 = *(const float4*)(Wb2 + kc + 16);
        }

        // two k8 steps
        #pragma unroll
        for (int kb = 0; kb < 16; kb += 8) {
            uint32_t afr[2][4], bfr[4][2];
            int ar = lane >> 2, ak = kb + (lane & 3);
            #pragma unroll
            for (int mi = 0; mi < 2; mi++) {
                int r = wm0 + mi*16 + ar;
                afr[mi][0] = As[r  ][ak];
                afr[mi][1] = As[r+8][ak];
                afr[mi][2] = As[r  ][ak+4];
                afr[mi][3] = As[r+8][ak+4];
            }
            #pragma unroll
            for (int ni = 0; ni < 4; ni++) {
                int r = wn0 + ni*8 + ar;
                bfr[ni][0] = Bs[r][ak];
                bfr[ni][1] = Bs[r][ak+4];
            }
            #pragma unroll
            for (int mi = 0; mi < 2; mi++)
                #pragma unroll
                for (int ni = 0; ni < 4; ni++)
                    mma_tf32(acc[mi][ni],
                             afr[mi][0], afr[mi][1], afr[mi][2], afr[mi][3],
                             bfr[ni][0], bfr[ni][1]);
        }
    }
}

// epilogue helper: per (mi,ni) block, c pairs at (rm, cn), (rm, cn+1), (rm+8, ...)
#define EPI_LOOP(body)                                                        \
    {                                                                         \
        int lane = threadIdx.x & 31, wrp = threadIdx.x >> 5;                  \
        int wm0 = (wrp >> 1) * 32, wn0 = (wrp & 1) * 32;                      \
        _Pragma("unroll")                                                     \
        for (int mi = 0; mi < 2; mi++) {                                      \
            _Pragma("unroll")                                                 \
            for (int ni = 0; ni < 4; ni++) {                                  \
                int rm = m0 + wm0 + mi*16 + (lane >> 2);                      \
                int cn = n0 + wn0 + ni*8 + (lane & 3)*2;                      \
                _Pragma("unroll")                                             \
                for (int hh2 = 0; hh2 < 2; hh2++) {                           \
                    int m = rm + hh2*8;                                       \
                    float v0 = acc[mi][ni][hh2*2 + 0];                        \
                    float v1 = acc[mi][ni][hh2*2 + 1];                        \
                    body                                                      \
                }                                                             \
            }                                                                 \
        }                                                                     \
    }

// ---------------- general NT GEMM (tensor core) ----------------
// MODE 0: C = AB    MODE 1: C = gelu(AB + bias)    MODE 2: C = AB + R
template <int MODE>
__global__ __launch_bounds__(128)
void gemm_nt_tc(const float* __restrict__ A, const float* __restrict__ W,
                const float* __restrict__ bias, const float* __restrict__ R,
                float* __restrict__ C, int N, int K)
{
    __shared__ uint32_t As[64][SM_STRIDE];
    __shared__ uint32_t Bs[64][SM_STRIDE];
    int m0 = blockIdx.y * 64, n0 = blockIdx.x * 64;
    float acc[2][4][4] = {};
    gemm_tc_body(A, W, K, K, 0, K, m0, n0, acc, As, Bs);

    EPI_LOOP({
        if (MODE == 1) { v0 = gelu_tanh(v0 + bias[cn]); v1 = gelu_tanh(v1 + bias[cn+1]); }
        if (MODE == 2) { v0 += R[(size_t)m*N + cn]; v1 += R[(size_t)m*N + cn + 1]; }
        C[(size_t)m*N + cn]     = v0;
        C[(size_t)m*N + cn + 1] = v1;
    })
}

// ---------------- fused Q/K/V projection (z selects matrix) ----------------
__global__ __launch_bounds__(128)
void gemm_qkv_tc(const float* __restrict__ A,
                 const float* __restrict__ Wq, const float* __restrict__ Wk,
                 const float* __restrict__ Wv)
{
    __shared__ uint32_t As[64][SM_STRIDE];
    __shared__ uint32_t Bs[64][SM_STRIDE];
    int z = blockIdx.z;
    const float* W = (z == 0) ? Wq : (z == 1) ? Wk : Wv;
    float* C = (z == 0) ? g_q : (z == 1) ? g_k : g_v;
    int m0 = blockIdx.y * 64, n0 = blockIdx.x * 64;
    float acc[2][4][4] = {};
    gemm_tc_body(A, W, DM, DM, 0, DM, m0, n0, acc, As, Bs);

    EPI_LOOP({
        C[(size_t)m*DM + cn]     = v0;
        C[(size_t)m*DM + cn + 1] = v1;
    })
}

// ---------------- split-K GEMM for W2 ----------------
__global__ __launch_bounds__(128)
void gemm_w2_splitk_tc(const float* __restrict__ A, const float* __restrict__ W)
{
    __shared__ uint32_t As[64][SM_STRIDE];
    __shared__ uint32_t Bs[64][SM_STRIDE];
    int z = blockIdx.z;
    int m0 = blockIdx.y * 64, n0 = blockIdx.x * 64;
    float acc[2][4][4] = {};
    gemm_tc_body(A, W, DFF, DFF, z*512, 512, m0, n0, acc, As, Bs);

    float* part = g_part + (size_t)z * (BB*TT*DM);
    EPI_LOOP({
        part[(size_t)m*DM + cn]     = v0;
        part[(size_t)m*DM + cn + 1] = v1;
    })
}

// ---------------- attention: one block per (q, head, batch) ----------------
__global__ __launch_bounds__(128)
void attn_kernel() {
    int qi = blockIdx.x;
    int hh = blockIdx.y;
    int b  = blockIdx.z;
    int tid = threadIdx.x;

    __shared__ float qs[DH];
    __shared__ float w[TT];
    __shared__ float r[TT];

    const float* qrow = g_q + (size_t)(b*TT + qi)*DM + hh*DH;
    if (tid < DH) qs[tid] = qrow[tid];
    __syncthreads();

    const float* krow = g_k + (size_t)(b*TT + tid)*DM + hh*DH;
    float s = 0.0f;
    #pragma unroll 16
    for (int d = 0; d < DH; d++) s += qs[d] * krow[d];
    float lg = (tid > qi) ? s * 0.125f : NEG_INF;

    r[tid] = lg; __syncthreads();
    for (int off = 64; off > 0; off >>= 1) {
        if (tid < off) r[tid] = fmaxf(r[tid], r[tid+off]);
        __syncthreads();
    }
    float m = r[0]; __syncthreads();

    float e = expf(lg - m);
    w[tid] = e; r[tid] = e; __syncthreads();
    for (int off = 64; off > 0; off >>= 1) {
        if (tid < off) r[tid] += r[tid+off];
        __syncthreads();
    }
    float inv = 1.0f / r[0];
    __syncthreads();

    if (tid < DH) {
        const float* vcol = g_v + (size_t)b*TT*DM + hh*DH + tid;
        float acc = 0.0f;
        #pragma unroll 8
        for (int j = 0; j < TT; j++) acc += w[j] * vcol[(size_t)j*DM];
        g_attn[(size_t)(b*TT + qi)*DM + hh*DH + tid] = acc * inv;
    }
}

// ---------------- layernorm over rows of 512 ----------------
// PART==0: x = X[row]; PART==1: x = X[row] + bias + sum_z part[z][row]
template <int PART>
__global__ __launch_bounds__(256)
void ln_kernel(const float* __restrict__ X, const float* __restrict__ bias,
               const float* __restrict__ gg, const float* __restrict__ bb,
               float* __restrict__ O)
{
    int rrow = blockIdx.x, tid = threadIdx.x;
    const float* x = X + (size_t)rrow * DM;
    float x0 = x[tid], x1 = x[tid + 256];
    if (PART) {
        x0 += bias[tid];
        x1 += bias[tid + 256];
        #pragma unroll
        for (int z = 0; z < 4; z++) {
            const float* p = g_part + (size_t)z*(BB*TT*DM) + (size_t)rrow*DM;
            x0 += p[tid];
            x1 += p[tid + 256];
        }
    }

    __shared__ float red[8];
    __shared__ float stats[2];
    int lane = tid & 31, warp = tid >> 5;

    float s = x0 + x1;
    for (int off = 16; off; off >>= 1) s += __shfl_down_sync(0xffffffffu, s, off);
    if (!lane) red[warp] = s;
    __syncthreads();
    if (tid == 0) {
        float t = 0; for (int i = 0; i < 8; i++) t += red[i];
        stats[0] = t * (1.0f / DM);
    }
    __syncthreads();
    float mu = stats[0];
    float d0 = x0 - mu, d1 = x1 - mu;
    s = d0*d0 + d1*d1;
    __syncthreads();
    for (int off = 16; off; off >>= 1) s += __shfl_down_sync(0xffffffffu, s, off);
    if (!lane) red[warp] = s;
    __syncthreads();
    if (tid == 0) {
        float t = 0; for (int i = 0; i < 8; i++) t += red[i];
        stats[1] = rsqrtf(t * (1.0f / DM) + 1e-5f);
    }
    __syncthreads();
    float rstd = stats[1];
    O[(size_t)rrow*DM + tid]       = d0 * rstd * gg[tid]       + bb[tid];
    O[(size_t)rrow*DM + tid + 256] = d1 * rstd * gg[tid + 256] + bb[tid + 256];
}

// ---------------- ctx-term for refine ----------------
__global__ __launch_bounds__(256)
void ctxterm_kernel(const float* __restrict__ Wr1, const float* __restrict__ br1,
                    const float* __restrict__ bemb, int step)
{
    int ridx = blockIdx.x * 8 + (threadIdx.x >> 5);
    int lane = threadIdx.x & 31;
    int b = ridx >> 11;
    int i = ridx & 2047;
    int ptr = THIST + step;
    const float* ctx = g_h + (size_t)(b*TT + ptr - 1)*DM;
    const float* w1  = Wr1 + (size_t)i * (2*DM);
    float s1 = 0.0f, s2 = 0.0f;
    for (int j = lane; j < DM; j += 32) {
        s1 += w1[j]      * bemb[j];
        s2 += w1[DM + j] * ctx[j];
    }
    for (int off = 16; off; off >>= 1) {
        s1 += __shfl_down_sync(0xffffffffu, s1, off);
        s2 += __shfl_down_sync(0xffffffffu, s2, off);
    }
    if (lane == 0) g_ctxterm[b*DFF + i] = s2 + SCALE_EMB * s1 + br1[i];
}

// ---------------- refine loop: one block per batch ----------------
__global__ __launch_bounds__(256)
void refine_kernel(const float* __restrict__ Wr2, const float* __restrict__ br2,
                   float* __restrict__ out, int step)
{
    int b = blockIdx.x;
    int tid = threadIdx.x;
    int ptr = THIST + step;

    __shared__ float cur[DIN];
    __shared__ float gact[DFF];

    if (tid < DIN) cur[tid] = g_buf[(size_t)(b*TT + ptr - 1)*DIN + tid];
    __syncthreads();

    for (int it = 0; it < NSUB; it++) {
        for (int i = tid; i < DFF; i += 256) {
            float s = g_ctxterm[b*DFF + i];
            const float* wf = g_wfused + i*DIN;
            #pragma unroll
            for (int m = 0; m < DIN; m++) s += wf[m] * cur[m];
            gact[i] = gelu_tanh(s);
        }
        __syncthreads();
        int warp = tid >> 5, lane = tid & 31;
        for (int m = warp*4; m < warp*4 + 4; m++) {
            float s = 0.0f;
            for (int i = lane; i < DFF; i += 32) s += Wr2[(size_t)m*DFF + i] * gact[i];
            for (int off = 16; off; off >>= 1) s += __shfl_down_sync(0xffffffffu, s, off);
            if (lane == 0) cur[m] += s + br2[m];
        }
        __syncthreads();
    }

    if (tid < DIN) {
        float v = cur[tid];
        g_buf[(size_t)(b*TT + ptr)*DIN + tid] = v;
        out[(size_t)(b*NSTEPS + step)*DIN + tid] = v;
    }
}

// ---------------- host orchestration ----------------
extern "C" void kernel_launch(void* const* d_in, const int* in_sizes, int n_in,
                              void* d_out, int out_size)
{
    const float* hist = (const float*)d_in[0];
    // d_in[1] = steps (int), fixed at 8
    const float* Wemb = (const float*)d_in[2];
    const float* bemb = (const float*)d_in[3];
    const float* Wq   = (const float*)d_in[4];
    const float* Wk   = (const float*)d_in[5];
    const float* Wv   = (const float*)d_in[6];
    const float* Wo   = (const float*)d_in[7];
    const float* ln1g = (const float*)d_in[8];
    const float* ln1b = (const float*)d_in[9];
    const float* W1   = (const float*)d_in[10];
    const float* b1   = (const float*)d_in[11];
    const float* W2   = (const float*)d_in[12];
    const float* b2   = (const float*)d_in[13];
    const float* ln2g = (const float*)d_in[14];
    const float* ln2b = (const float*)d_in[15];
    const float* Wr1  = (const float*)d_in[16];
    const float* br1  = (const float*)d_in[17];
    const float* Wr2  = (const float*)d_in[18];
    const float* br2  = (const float*)d_in[19];
    float* out = (float*)d_out;

    float *p_h, *p_attn, *p_tmp, *p_ff;
    cudaGetSymbolAddress((void**)&p_h,    g_h);
    cudaGetSymbolAddress((void**)&p_attn, g_attn);
    cudaGetSymbolAddress((void**)&p_tmp,  g_tmp);
    cudaGetSymbolAddress((void**)&p_ff,   g_ff);

    const int M = BB * TT;   // 512

    init_kernel<<<64, 256>>>(hist);
    wfused_kernel<<<256, 256>>>(Wr1, Wemb);

    for (int step = 0; step < NSTEPS; step++) {
        embed_kernel<<<M, 128>>>(Wemb, bemb);

        for (int l = 0; l < NL; l++) {
            const float* wq = Wq + (size_t)l*DM*DM;
            const float* wk = Wk + (size_t)l*DM*DM;
            const float* wv = Wv + (size_t)l*DM*DM;
            const float* wo = Wo + (size_t)l*DM*DM;
            const float* w1 = W1 + (size_t)l*DFF*DM;
            const float* w2 = W2 + (size_t)l*DM*DFF;

            dim3 gqkv(DM/64, M/64, 3);  // 192 CTAs
            dim3 g512(DM/64, M/64);     // 64 CTAs
            dim3 gff(DFF/64, M/64);     // 256 CTAs
            dim3 gw2(DM/64, M/64, 4);   // split-K: 256 CTAs

            gemm_qkv_tc<<<gqkv, 128>>>(p_h, wq, wk, wv);
            attn_kernel<<<dim3(TT, NH, BB), 128>>>();

            gemm_nt_tc<2><<<g512, 128>>>(p_attn, wo, nullptr, p_h, p_tmp, DM, DM);
            ln_kernel<0><<<M, 256>>>(p_tmp, nullptr, ln1g + l*DM, ln1b + l*DM, p_h);

            gemm_nt_tc<1><<<gff, 128>>>(p_h, w1, b1 + l*DFF, nullptr, p_ff, DFF, DM);
            gemm_w2_splitk_tc<<<gw2, 128>>>(p_ff, w2);
            ln_kernel<1><<<M, 256>>>(p_h, b2 + l*DM, ln2g + l*DM, ln2b + l*DM, p_h);
        }

        ctxterm_kernel<<<1024, 256>>>(Wr1, br1, bemb, step);
        refine_kernel<<<BB, 256>>>(Wr2, br2, out, step);
    }
}

// round 6
// speedup vs baseline: 1.4387x; 1.1201x over previous
#include <cuda_runtime.h>
#include <cuda_bf16.h>
#include <cstdint>

// ---------------- problem constants ----------------
#define BB      4
#define TT      128
#define THIST   120
#define NSTEPS  8
#define DM      512
#define NH      8
#define DH      64
#define DFF     2048
#define DIN     32
#define NL      4
#define NSUB    5

#define SCALE_EMB 22.627416997969522f   // sqrt(512)
#define NEG_INF  (-3.402823466e38f)
#define LN10000  9.210340371976184f

// ---------------- device scratch (static, no allocation) ----------------
__device__ float g_buf [BB*TT*DIN];
__device__ float g_h   [BB*TT*DM];
__device__ float g_q   [BB*TT*DM];
__device__ float g_k   [BB*TT*DM];
__device__ float g_v   [BB*TT*DM];
__device__ float g_attn[BB*TT*DM];
__device__ float g_ff  [BB*TT*DFF];
__device__ float g_part[4*BB*TT*DM];    // split-K partials (wo uses 2, w2 uses 4)
__device__ float g_wfused [DFF*DIN];
__device__ float g_ctxterm[BB*DFF];

// ---------------- helpers ----------------
__device__ __forceinline__ float gelu_tanh(float x) {
    float x3 = x * x * x;
    float t  = tanhf(0.7978845608028654f * (x + 0.044715f * x3));
    return 0.5f * x * (1.0f + t);
}

__device__ __forceinline__ uint32_t f2tf32(float x) {
    uint32_t r;
    asm("cvt.rna.tf32.f32 %0, %1;" : "=r"(r) : "f"(x));
    return r;
}

__device__ __forceinline__ void mma_tf32(float c[4],
    uint32_t a0, uint32_t a1, uint32_t a2, uint32_t a3,
    uint32_t b0, uint32_t b1)
{
    asm volatile(
        "mma.sync.aligned.m16n8k8.row.col.f32.tf32.tf32.f32 "
        "{%0,%1,%2,%3}, {%4,%5,%6,%7}, {%8,%9}, {%0,%1,%2,%3};"
        : "+f"(c[0]), "+f"(c[1]), "+f"(c[2]), "+f"(c[3])
        : "r"(a0), "r"(a1), "r"(a2), "r"(a3), "r"(b0), "r"(b1));
}

// ---------------- init: buf = [history ; zeros] ----------------
__global__ void init_kernel(const float* __restrict__ hist) {
    int idx = blockIdx.x * 256 + threadIdx.x;
    if (idx >= BB*TT*DIN) return;
    int b = idx >> 12;
    int t = (idx >> 5) & 127;
    int k = idx & 31;
    g_buf[idx] = (t < THIST) ? hist[(b*THIST + t)*DIN + k] : 0.0f;
}

// ---------------- precompute Wfused = scale * Wr1[:, :512] @ W_emb ----------------
__global__ void wfused_kernel(const float* __restrict__ Wr1, const float* __restrict__ Wemb) {
    int idx = blockIdx.x * 256 + threadIdx.x;
    int i = idx >> 5;
    int m = idx & 31;
    const float* w = Wr1 + (size_t)i * (2*DM);
    float s = 0.0f;
    #pragma unroll 8
    for (int j = 0; j < DM; j++) s += w[j] * Wemb[j*DIN + m];
    g_wfused[i*DIN + m] = s * SCALE_EMB;
}

// ---------------- embedding + positional encoding ----------------
__global__ void embed_kernel(const float* __restrict__ Wemb, const float* __restrict__ bemb) {
    int bt = blockIdx.x;                 // 0..511
    int t  = bt & 127;
    __shared__ float row[DIN];
    if (threadIdx.x < DIN) row[threadIdx.x] = g_buf[bt*DIN + threadIdx.x];
    __syncthreads();
    for (int d = threadIdx.x; d < DM; d += blockDim.x) {
        float s = bemb[d];
        const float* w = Wemb + d*DIN;
        #pragma unroll
        for (int k = 0; k < DIN; k++) s += row[k] * w[k];
        int i = d >> 1;
        float div = expf((float)(2*i) * (-LN10000 / (float)DM));
        float ang = (float)t * div;
        float pe  = (d & 1) ? cosf(ang) : sinf(ang);
        g_h[bt*DM + d] = s * SCALE_EMB + pe;
    }
}

// ================= tf32 tensor-core tile body (256 threads) =================
// CTA = 256 threads (8 warps, 2x4 warp grid), tile 64x64, K chunk 32.
// Warp computes 32x16 sub-tile: 2 m16 blocks x 2 n8 blocks.
// Smem stride 36 words: frag reads hit banks 4q+t (conflict-free);
// 128-bit stores conflict-free per 8-lane phase.
#define SM_STRIDE 36

__device__ __forceinline__ void gemm_tc_body(
    const float* __restrict__ A, const float* __restrict__ W,
    int lda, int ldw, int kbeg, int klen,
    int m0, int n0, float acc[2][2][4],
    uint32_t (*As)[SM_STRIDE], uint32_t (*Bs)[SM_STRIDE])
{
    int tid  = threadIdx.x;       // 0..255
    int lane = tid & 31;
    int wrp  = tid >> 5;
    int wm0 = (wrp >> 2) * 32;
    int wn0 = (wrp & 3) * 16;

    // loader: chunk is 64 rows x 32 cols; thread loads rows {lrow, lrow+32}, 4 cols
    int lrow = tid >> 3;          // 0..31
    int lcol = (tid & 7) * 4;     // 0,4,...,28

    const float* Ab  = A + (size_t)(m0 + lrow) * lda + kbeg + lcol;
    const float* Ab2 = Ab + (size_t)32 * lda;
    const float* Wb  = W + (size_t)(n0 + lrow) * ldw + kbeg + lcol;
    const float* Wb2 = Wb + (size_t)32 * ldw;

    float4 pa0 = *(const float4*)(Ab);
    float4 pa1 = *(const float4*)(Ab2);
    float4 pb0 = *(const float4*)(Wb);
    float4 pb1 = *(const float4*)(Wb2);

    for (int kc = 0; kc < klen; kc += 32) {
        __syncthreads();
        {
            uint4 u;
            u.x=f2tf32(pa0.x); u.y=f2tf32(pa0.y); u.z=f2tf32(pa0.z); u.w=f2tf32(pa0.w);
            *(uint4*)&As[lrow][lcol] = u;
            u.x=f2tf32(pa1.x); u.y=f2tf32(pa1.y); u.z=f2tf32(pa1.z); u.w=f2tf32(pa1.w);
            *(uint4*)&As[lrow+32][lcol] = u;
            u.x=f2tf32(pb0.x); u.y=f2tf32(pb0.y); u.z=f2tf32(pb0.z); u.w=f2tf32(pb0.w);
            *(uint4*)&Bs[lrow][lcol] = u;
            u.x=f2tf32(pb1.x); u.y=f2tf32(pb1.y); u.z=f2tf32(pb1.z); u.w=f2tf32(pb1.w);
            *(uint4*)&Bs[lrow+32][lcol] = u;
        }
        __syncthreads();

        if (kc + 32 < klen) {
            pa0 = *(const float4*)(Ab  + kc + 32);
            pa1 = *(const float4*)(Ab2 + kc + 32);
            pb0 = *(const float4*)(Wb  + kc + 32);
            pb1 = *(const float4*)(Wb2 + kc + 32);
        }

        int ar = lane >> 2, at = lane & 3;
        #pragma unroll
        for (int kb = 0; kb < 32; kb += 8) {
            uint32_t afr[2][4], bfr[2][2];
            int ak = kb + at;
            #pragma unroll
            for (int mi = 0; mi < 2; mi++) {
                int r = wm0 + mi*16 + ar;
                afr[mi][0] = As[r  ][ak];
                afr[mi][1] = As[r+8][ak];
                afr[mi][2] = As[r  ][ak+4];
                afr[mi][3] = As[r+8][ak+4];
            }
            #pragma unroll
            for (int ni = 0; ni < 2; ni++) {
                int r = wn0 + ni*8 + ar;
                bfr[ni][0] = Bs[r][ak];
                bfr[ni][1] = Bs[r][ak+4];
            }
            #pragma unroll
            for (int mi = 0; mi < 2; mi++)
                #pragma unroll
                for (int ni = 0; ni < 2; ni++)
                    mma_tf32(acc[mi][ni],
                             afr[mi][0], afr[mi][1], afr[mi][2], afr[mi][3],
                             bfr[ni][0], bfr[ni][1]);
        }
    }
}

#define EPI_LOOP(body)                                                        \
    {                                                                         \
        int lane = threadIdx.x & 31, wrp = threadIdx.x >> 5;                  \
        int wm0 = (wrp >> 2) * 32, wn0 = (wrp & 3) * 16;                      \
        _Pragma("unroll")                                                     \
        for (int mi = 0; mi < 2; mi++) {                                      \
            _Pragma("unroll")                                                 \
            for (int ni = 0; ni < 2; ni++) {                                  \
                int rm = m0 + wm0 + mi*16 + (lane >> 2);                      \
                int cn = n0 + wn0 + ni*8 + (lane & 3)*2;                      \
                _Pragma("unroll")                                             \
                for (int hh2 = 0; hh2 < 2; hh2++) {                           \
                    int m = rm + hh2*8;                                       \
                    float v0 = acc[mi][ni][hh2*2 + 0];                        \
                    float v1 = acc[mi][ni][hh2*2 + 1];                        \
                    body                                                      \
                }                                                             \
            }                                                                 \
        }                                                                     \
    }

// ---------------- general NT GEMM ----------------
// MODE 0: C = AB     MODE 1: C = gelu(AB + bias)
template <int MODE>
__global__ __launch_bounds__(256)
void gemm_nt_tc(const float* __restrict__ A, const float* __restrict__ W,
                const float* __restrict__ bias,
                float* __restrict__ C, int N, int K)
{
    __shared__ __align__(16) uint32_t As[64][SM_STRIDE];
    __shared__ __align__(16) uint32_t Bs[64][SM_STRIDE];
    int m0 = blockIdx.y * 64, n0 = blockIdx.x * 64;
    float acc[2][2][4] = {};
    gemm_tc_body(A, W, K, K, 0, K, m0, n0, acc, As, Bs);

    EPI_LOOP({
        if (MODE == 1) { v0 = gelu_tanh(v0 + bias[cn]); v1 = gelu_tanh(v1 + bias[cn+1]); }
        C[(size_t)m*N + cn]     = v0;
        C[(size_t)m*N + cn + 1] = v1;
    })
}

// ---------------- fused Q/K/V projection ----------------
__global__ __launch_bounds__(256)
void gemm_qkv_tc(const float* __restrict__ A,
                 const float* __restrict__ Wq, const float* __restrict__ Wk,
                 const float* __restrict__ Wv)
{
    __shared__ __align__(16) uint32_t As[64][SM_STRIDE];
    __shared__ __align__(16) uint32_t Bs[64][SM_STRIDE];
    int z = blockIdx.z;
    const float* W = (z == 0) ? Wq : (z == 1) ? Wk : Wv;
    float* C = (z == 0) ? g_q : (z == 1) ? g_k : g_v;
    int m0 = blockIdx.y * 64, n0 = blockIdx.x * 64;
    float acc[2][2][4] = {};
    gemm_tc_body(A, W, DM, DM, 0, DM, m0, n0, acc, As, Bs);

    EPI_LOOP({
        C[(size_t)m*DM + cn]     = v0;
        C[(size_t)m*DM + cn + 1] = v1;
    })
}

// ---------------- split-K GEMM (N = 512): wo (K=512,split2), w2 (K=2048,split4) ----------------
__global__ __launch_bounds__(256)
void gemm_splitk_tc(const float* __restrict__ A, const float* __restrict__ W,
                    int ld, int klen)
{
    __shared__ __align__(16) uint32_t As[64][SM_STRIDE];
    __shared__ __align__(16) uint32_t Bs[64][SM_STRIDE];
    int z = blockIdx.z;
    int m0 = blockIdx.y * 64, n0 = blockIdx.x * 64;
    float acc[2][2][4] = {};
    gemm_tc_body(A, W, ld, ld, z*klen, klen, m0, n0, acc, As, Bs);

    float* part = g_part + (size_t)z * (BB*TT*DM);
    EPI_LOOP({
        part[(size_t)m*DM + cn]     = v0;
        part[(size_t)m*DM + cn + 1] = v1;
    })
}

// ---------------- attention: one block per (q, head, batch) ----------------
__global__ __launch_bounds__(128)
void attn_kernel() {
    int qi = blockIdx.x;
    int hh = blockIdx.y;
    int b  = blockIdx.z;
    int tid = threadIdx.x;
    int lane = tid & 31, wrp = tid >> 5;

    __shared__ float qs[DH];
    __shared__ float wsh[TT];
    __shared__ float redm[4];
    __shared__ float reds[4];

    const float* qrow = g_q + (size_t)(b*TT + qi)*DM + hh*DH;
    if (tid < DH) qs[tid] = qrow[tid];
    __syncthreads();

    const float* krow = g_k + (size_t)(b*TT + tid)*DM + hh*DH;
    float s = 0.0f;
    #pragma unroll 16
    for (int d = 0; d < DH; d++) s += qs[d] * krow[d];
    float lg = (tid > qi) ? s * 0.125f : NEG_INF;

    float m = lg;
    #pragma unroll
    for (int off = 16; off; off >>= 1) m = fmaxf(m, __shfl_xor_sync(0xffffffffu, m, off));
    if (lane == 0) redm[wrp] = m;
    __syncthreads();
    m = fmaxf(fmaxf(redm[0], redm[1]), fmaxf(redm[2], redm[3]));

    float e = expf(lg - m);
    wsh[tid] = e;
    float sm = e;
    #pragma unroll
    for (int off = 16; off; off >>= 1) sm += __shfl_xor_sync(0xffffffffu, sm, off);
    if (lane == 0) reds[wrp] = sm;
    __syncthreads();
    float inv = 1.0f / (reds[0] + reds[1] + reds[2] + reds[3]);

    if (tid < DH) {
        const float* vcol = g_v + (size_t)b*TT*DM + hh*DH + tid;
        float acc = 0.0f;
        #pragma unroll 8
        for (int j = 0; j < TT; j++) acc += wsh[j] * vcol[(size_t)j*DM];
        g_attn[(size_t)(b*TT + qi)*DM + hh*DH + tid] = acc * inv;
    }
}

// ---------------- layernorm (+ fused split-K reduction + residual + bias) ----------------
// x = X[row] (+bias) + sum_{z<NPART} part[z][row]
template <int NPART>
__global__ __launch_bounds__(256)
void ln_kernel(const float* __restrict__ X, const float* __restrict__ bias,
               const float* __restrict__ gg, const float* __restrict__ bb,
               float* __restrict__ O)
{
    int rrow = blockIdx.x, tid = threadIdx.x;
    const float* x = X + (size_t)rrow * DM;
    float x0 = x[tid], x1 = x[tid + 256];
    if (bias) {
        x0 += bias[tid];
        x1 += bias[tid + 256];
    }
    #pragma unroll
    for (int z = 0; z < NPART; z++) {
        const float* p = g_part + (size_t)z*(BB*TT*DM) + (size_t)rrow*DM;
        x0 += p[tid];
        x1 += p[tid + 256];
    }

    __shared__ float red[8];
    __shared__ float stats[2];
    int lane = tid & 31, warp = tid >> 5;

    float s = x0 + x1;
    for (int off = 16; off; off >>= 1) s += __shfl_down_sync(0xffffffffu, s, off);
    if (!lane) red[warp] = s;
    __syncthreads();
    if (tid == 0) {
        float t = 0; for (int i = 0; i < 8; i++) t += red[i];
        stats[0] = t * (1.0f / DM);
    }
    __syncthreads();
    float mu = stats[0];
    float d0 = x0 - mu, d1 = x1 - mu;
    s = d0*d0 + d1*d1;
    __syncthreads();
    for (int off = 16; off; off >>= 1) s += __shfl_down_sync(0xffffffffu, s, off);
    if (!lane) red[warp] = s;
    __syncthreads();
    if (tid == 0) {
        float t = 0; for (int i = 0; i < 8; i++) t += red[i];
        stats[1] = rsqrtf(t * (1.0f / DM) + 1e-5f);
    }
    __syncthreads();
    float rstd = stats[1];
    O[(size_t)rrow*DM + tid]       = d0 * rstd * gg[tid]       + bb[tid];
    O[(size_t)rrow*DM + tid + 256] = d1 * rstd * gg[tid + 256] + bb[tid + 256];
}

// ---------------- ctx-term for refine ----------------
__global__ __launch_bounds__(256)
void ctxterm_kernel(const float* __restrict__ Wr1, const float* __restrict__ br1,
                    const float* __restrict__ bemb, int step)
{
    int ridx = blockIdx.x * 8 + (threadIdx.x >> 5);
    int lane = threadIdx.x & 31;
    int b = ridx >> 11;
    int i = ridx & 2047;
    int ptr = THIST + step;
    const float* ctx = g_h + (size_t)(b*TT + ptr - 1)*DM;
    const float* w1  = Wr1 + (size_t)i * (2*DM);
    float s1 = 0.0f, s2 = 0.0f;
    for (int j = lane; j < DM; j += 32) {
        s1 += w1[j]      * bemb[j];
        s2 += w1[DM + j] * ctx[j];
    }
    for (int off = 16; off; off >>= 1) {
        s1 += __shfl_down_sync(0xffffffffu, s1, off);
        s2 += __shfl_down_sync(0xffffffffu, s2, off);
    }
    if (lane == 0) g_ctxterm[b*DFF + i] = s2 + SCALE_EMB * s1 + br1[i];
}

// ---------------- refine loop: one block per batch ----------------
__global__ __launch_bounds__(256)
void refine_kernel(const float* __restrict__ Wr2, const float* __restrict__ br2,
                   float* __restrict__ out, int step)
{
    int b = blockIdx.x;
    int tid = threadIdx.x;
    int ptr = THIST + step;

    __shared__ float cur[DIN];
    __shared__ float gact[DFF];

    if (tid < DIN) cur[tid] = g_buf[(size_t)(b*TT + ptr - 1)*DIN + tid];
    __syncthreads();

    for (int it = 0; it < NSUB; it++) {
        for (int i = tid; i < DFF; i += 256) {
            float s = g_ctxterm[b*DFF + i];
            const float* wf = g_wfused + i*DIN;
            #pragma unroll
            for (int m = 0; m < DIN; m++) s += wf[m] * cur[m];
            gact[i] = gelu_tanh(s);
        }
        __syncthreads();
        int warp = tid >> 5, lane = tid & 31;
        for (int m = warp*4; m < warp*4 + 4; m++) {
            float s = 0.0f;
            for (int i = lane; i < DFF; i += 32) s += Wr2[(size_t)m*DFF + i] * gact[i];
            for (int off = 16; off; off >>= 1) s += __shfl_down_sync(0xffffffffu, s, off);
            if (lane == 0) cur[m] += s + br2[m];
        }
        __syncthreads();
    }

    if (tid < DIN) {
        float v = cur[tid];
        g_buf[(size_t)(b*TT + ptr)*DIN + tid] = v;
        out[(size_t)(b*NSTEPS + step)*DIN + tid] = v;
    }
}

// ---------------- host orchestration ----------------
extern "C" void kernel_launch(void* const* d_in, const int* in_sizes, int n_in,
                              void* d_out, int out_size)
{
    const float* hist = (const float*)d_in[0];
    // d_in[1] = steps (int), fixed at 8
    const float* Wemb = (const float*)d_in[2];
    const float* bemb = (const float*)d_in[3];
    const float* Wq   = (const float*)d_in[4];
    const float* Wk   = (const float*)d_in[5];
    const float* Wv   = (const float*)d_in[6];
    const float* Wo   = (const float*)d_in[7];
    const float* ln1g = (const float*)d_in[8];
    const float* ln1b = (const float*)d_in[9];
    const float* W1   = (const float*)d_in[10];
    const float* b1   = (const float*)d_in[11];
    const float* W2   = (const float*)d_in[12];
    const float* b2   = (const float*)d_in[13];
    const float* ln2g = (const float*)d_in[14];
    const float* ln2b = (const float*)d_in[15];
    const float* Wr1  = (const float*)d_in[16];
    const float* br1  = (const float*)d_in[17];
    const float* Wr2  = (const float*)d_in[18];
    const float* br2  = (const float*)d_in[19];
    float* out = (float*)d_out;

    float *p_h, *p_attn, *p_ff;
    cudaGetSymbolAddress((void**)&p_h,    g_h);
    cudaGetSymbolAddress((void**)&p_attn, g_attn);
    cudaGetSymbolAddress((void**)&p_ff,   g_ff);

    const int M = BB * TT;   // 512

    init_kernel<<<64, 256>>>(hist);
    wfused_kernel<<<256, 256>>>(Wr1, Wemb);

    for (int step = 0; step < NSTEPS; step++) {
        embed_kernel<<<M, 128>>>(Wemb, bemb);

        for (int l = 0; l < NL; l++) {
            const float* wq = Wq + (size_t)l*DM*DM;
            const float* wk = Wk + (size_t)l*DM*DM;
            const float* wv = Wv + (size_t)l*DM*DM;
            const float* wo = Wo + (size_t)l*DM*DM;
            const float* w1 = W1 + (size_t)l*DFF*DM;
            const float* w2 = W2 + (size_t)l*DM*DFF;

            dim3 gqkv(DM/64, M/64, 3);  // 192 CTAs
            dim3 gwo (DM/64, M/64, 2);  // split-K=2: 128 CTAs
            dim3 gff (DFF/64, M/64);    // 256 CTAs
            dim3 gw2 (DM/64, M/64, 4);  // split-K=4: 256 CTAs

            gemm_qkv_tc<<<gqkv, 256>>>(p_h, wq, wk, wv);
            attn_kernel<<<dim3(TT, NH, BB), 128>>>();

            gemm_splitk_tc<<<gwo, 256>>>(p_attn, wo, DM, 256);
            ln_kernel<2><<<M, 256>>>(p_h, nullptr, ln1g + l*DM, ln1b + l*DM, p_h);

            gemm_nt_tc<1><<<gff, 256>>>(p_h, w1, b1 + l*DFF, p_ff, DFF, DM);
            gemm_splitk_tc<<<gw2, 256>>>(p_ff, w2, DFF, 512);
            ln_kernel<4><<<M, 256>>>(p_h, b2 + l*DM, ln2g + l*DM, ln2b + l*DM, p_h);
        }

        ctxterm_kernel<<<1024, 256>>>(Wr1, br1, bemb, step);
        refine_kernel<<<BB, 256>>>(Wr2, br2, out, step);
    }
}